// round 13
// baseline (speedup 1.0000x reference)
#include <cuda_runtime.h>
#include <cuda_fp16.h>
#include <cstdint>
#include <math.h>

// Problem constants
constexpr int   D       = 2048;
constexpr int   F       = 256;
constexpr float ALPHA   = 0.005f;   // SINKHORN_ALPHA
constexpr float STOPTHR = 0.005f;
constexpr float EPSF    = 1e-16f;
constexpr int   MAXIT   = 500;

// Launch shapes
constexpr int NB   = 128;         // persistent sinkhorn blocks
constexpr int NT   = 256;
constexpr int RPB  = D / NB;      // 16 rows per block
constexpr int NKB  = 256;
constexpr int NBLK = 136;         // triangular 128x128 tile count: 16*17/2
constexpr int NCTR = 16;          // spread barrier counters (one per 128B line)
constexpr int ARR_PER_CTR = NB / NCTR;   // 8 arrivals per counter per epoch

// GEMM smem: two 128x68 u32 tiles (tf32, K-chunk=64) -> 69.6KB -> 2 CTAs/SM,
// all 272 blocks in ONE wave. Epilogue reuses the union as 128x132 f32.
constexpr int PITCH2  = 68;                   // mma tile pitch (words)
constexpr int TILEW2  = 128 * PITCH2;         // words per tile
constexpr int PITCH_C = 132;                  // epilogue pitch (words)
constexpr int GEMM_SMEM = 2 * TILEW2 * 4;     // 69632 bytes (>= 128*132*4 = 67584)

typedef unsigned long long ull;

// ---------------- device scratch ----------------
__device__ __half d_Kh[(size_t)D * D];    // 8 MB: K = exp(-alpha*C), fp16, symmetric
__device__ float  d_G[(size_t)D * D];     // 16 MB: Ghat = ehat ehat^T, symmetric
__device__ float  d_ehat[D * F];
__device__ float  d_sq[D];
__device__ float  d_invr[D];
__device__ float  d_u[D];
__device__ float  d_v[D];
__device__ float  d_errpart[12 * NB];
__device__ double d_part[3 * NKB];
__device__ unsigned d_cnts[NCTR * 32];    // 16 counters, 128B apart (own L2 lines)

// ---------------- f32x2 helpers (used in sinkhorn dot) ----------------
__device__ __forceinline__ ull pk2(float lo, float hi) {
    ull r; asm("mov.b64 %0,{%1,%2};" : "=l"(r) : "f"(lo), "f"(hi)); return r;
}
__device__ __forceinline__ float2 up2(ull v) {
    float2 f; asm("mov.b64 {%0,%1},%2;" : "=f"(f.x), "=f"(f.y) : "l"(v)); return f;
}
__device__ __forceinline__ void fma2(ull& d, ull a, ull b) {
    asm("fma.rn.f32x2 %0,%1,%2,%0;" : "+l"(d) : "l"(a), "l"(b));
}
__device__ __forceinline__ ull h2f2(unsigned h) {
    const float2 f = __half22float2(*reinterpret_cast<const __half2*>(&h));
    return pk2(f.x, f.y);
}

// ---------------- tf32 mma helpers ----------------
__device__ __forceinline__ uint32_t f2tf32(float f) {
    uint32_t r; asm("cvt.rna.tf32.f32 %0,%1;" : "=r"(r) : "f"(f)); return r;
}
__device__ __forceinline__ void mma_tf32(float* c, const uint32_t* a, const uint32_t* b) {
    asm("mma.sync.aligned.m16n8k8.row.col.f32.tf32.tf32.f32 "
        "{%0,%1,%2,%3},{%4,%5,%6,%7},{%8,%9},{%0,%1,%2,%3};"
        : "+f"(c[0]), "+f"(c[1]), "+f"(c[2]), "+f"(c[3])
        : "r"(a[0]), "r"(a[1]), "r"(a[2]), "r"(a[3]), "r"(b[0]), "r"(b[1]));
}

__device__ __forceinline__ float warp_red(float s) {
#pragma unroll
    for (int o = 16; o; o >>= 1) s += __shfl_xor_sync(0xffffffffu, s, o);
    return s;
}

// Grid barrier v6: arrival/poll DECONGESTION.
// All five previous barrier variants cost ~10us REGARDLESS of mechanism; the
// shared trait was 128 arrivals colliding with a chip-wide poll-load backlog on
// the same L2 line(s). Fix both sides:
//  - arrivals spread over 16 counters on separate 128B lines (8 arrivals each),
//  - single poller per block, with a ~256-cycle dependent-FMA backoff between
//    poll sweeps so the poll stream cannot starve the arriving REDs.
__device__ __forceinline__ void gbar(unsigned ep, int tid, int bid) {
    __syncthreads();
    if (tid == 0) {
        asm volatile("red.release.gpu.global.add.u32 [%0], 1;"
                     :: "l"(&d_cnts[(bid & (NCTR - 1)) * 32]) : "memory");
        const unsigned tgt = ep * ARR_PER_CTR;
        float bk = 1.0f + (float)(int)(ep & 1) * 1e-7f;   // runtime-opaque seed
        for (;;) {
            int ok = 1;
#pragma unroll
            for (int c = 0; c < NCTR; c++) {
                unsigned v;
                asm volatile("ld.acquire.gpu.global.u32 %0, [%1];"
                             : "=r"(v) : "l"(&d_cnts[c * 32]) : "memory");
                if (v < tgt) ok = 0;
            }
            if (ok) break;
            // ~256-cycle dependent-FMA backoff (deterministic, no nanosleep)
#pragma unroll
            for (int i = 0; i < 64; i++) bk = fmaf(bk, 1.0000001f, 1e-9f);
            if (__float_as_uint(bk) == 0u) break;   // opaque, never taken
        }
    }
    __syncthreads();
}

// ---------------- prep: sq, ehat, counter reset ----------------
__global__ void __launch_bounds__(F) prep(const float* __restrict__ theta,
                                          const float* __restrict__ emb) {
    const int row = blockIdx.x, tid = threadIdx.x;
    if (tid == 0 && row < NCTR) d_cnts[row * 32] = 0u;

    const float t = theta[row * F + tid];
    const float e = emb[row * F + tid];
    float a = t * t, b = e * e;
#pragma unroll
    for (int o = 16; o; o >>= 1) {
        a += __shfl_xor_sync(0xffffffffu, a, o);
        b += __shfl_xor_sync(0xffffffffu, b, o);
    }
    __shared__ float sa[8], sb[8];
    __shared__ float s_inv;
    const int wid = tid >> 5, lane = tid & 31;
    if (lane == 0) { sa[wid] = a; sb[wid] = b; }
    __syncthreads();
    if (tid == 0) {
        float ta = 0.f, tb = 0.f;
#pragma unroll
        for (int i = 0; i < 8; i++) { ta += sa[i]; tb += sb[i]; }
        d_sq[row] = ta;
        s_inv = 1.0f / sqrtf(tb);
    }
    __syncthreads();
    d_ehat[row * F + tid] = e * s_inv;
}

// ---------------- symmetric fused GEMM — tf32 tensor cores --------------
// bid in [0, NBLK)      : K (fp16 out) = exp(-alpha*max(sq_i+sq_j-2*theta theta^T,0))
// bid in [NBLK, 2*NBLK) : Ghat (fp32 out) = ehat ehat^T
// 128x128 tile per block, 8 warps x (64x32) warp tiles of m16n8k8 tf32 mma.
// K-chunk = 64 -> 69.6KB smem -> 2 CTAs/SM -> single wave for all 272 blocks.
__global__ void __launch_bounds__(256, 2) gemm_sym(const float* __restrict__ theta) {
    extern __shared__ uint32_t smw[];
    uint32_t* As = smw;             // [128][PITCH2] tf32
    uint32_t* Bs = smw + TILEW2;    // [128][PITCH2] tf32

    const int bid = blockIdx.x;
    const bool modeK = (bid < NBLK);
    const int tb = modeK ? bid : bid - NBLK;
    const float* __restrict__ X = modeK ? theta : (const float*)d_ehat;

    // triangular index -> (ib, jb), ib >= jb
    int ib = (int)((sqrtf(8.0f * (float)tb + 1.0f) - 1.0f) * 0.5f);
    while ((ib + 1) * (ib + 2) / 2 <= tb) ib++;
    while (ib * (ib + 1) / 2 > tb) ib--;
    const int jb = tb - ib * (ib + 1) / 2;
    const int r0 = ib * 128, c0 = jb * 128;

    const int tid  = threadIdx.x;
    const int wid  = tid >> 5, lane = tid & 31;
    const int g    = lane >> 2, t = lane & 3;   // fragment group / thread-in-group
    const int wm   = wid >> 2,  wn = wid & 3;   // warp tile: rows wm*64, cols wn*32

    float c[4][4][4];
#pragma unroll
    for (int am = 0; am < 4; am++)
#pragma unroll
        for (int bn = 0; bn < 4; bn++)
#pragma unroll
            for (int e = 0; e < 4; e++) c[am][bn][e] = 0.0f;

    for (int kc = 0; kc < 4; kc++) {           // four 64-wide K chunks
        // stage: fp32 -> tf32 into padded smem (k-contiguous rows)
        for (int idx = tid; idx < 128 * 16; idx += 256) {
            const int r = idx >> 4, q = (idx & 15) * 4;
            const float4 av = *(const float4*)(X + (size_t)(r0 + r) * F + kc * 64 + q);
            uint4 ua;
            ua.x = f2tf32(av.x); ua.y = f2tf32(av.y);
            ua.z = f2tf32(av.z); ua.w = f2tf32(av.w);
            *(uint4*)&As[r * PITCH2 + q] = ua;
            const float4 bv = *(const float4*)(X + (size_t)(c0 + r) * F + kc * 64 + q);
            uint4 ub;
            ub.x = f2tf32(bv.x); ub.y = f2tf32(bv.y);
            ub.z = f2tf32(bv.z); ub.w = f2tf32(bv.w);
            *(uint4*)&Bs[r * PITCH2 + q] = ub;
        }
        __syncthreads();

#pragma unroll 4
        for (int s = 0; s < 8; s++) {          // k-steps of 8 within the chunk
            uint32_t a[4][4], b[4][2];
#pragma unroll
            for (int am = 0; am < 4; am++) {
                const uint32_t* p = As + (wm * 64 + am * 16 + g) * PITCH2 + s * 8 + t;
                a[am][0] = p[0];
                a[am][1] = p[8 * PITCH2];
                a[am][2] = p[4];
                a[am][3] = p[8 * PITCH2 + 4];
            }
#pragma unroll
            for (int bn = 0; bn < 4; bn++) {
                const uint32_t* p = Bs + (wn * 32 + bn * 8 + g) * PITCH2 + s * 8 + t;
                b[bn][0] = p[0];
                b[bn][1] = p[4];
            }
#pragma unroll
            for (int am = 0; am < 4; am++)
#pragma unroll
                for (int bn = 0; bn < 4; bn++)
                    mma_tf32(c[am][bn], a[am], b[bn]);
        }
        __syncthreads();                        // before next stage overwrites
    }

    // ---- epilogue: fragments -> smem (reuse whole region), then coalesced stores
    float* Ct = (float*)smw;                    // [128][PITCH_C]
#pragma unroll
    for (int am = 0; am < 4; am++) {
        const int r = wm * 64 + am * 16 + g;
#pragma unroll
        for (int bn = 0; bn < 4; bn++) {
            const int cc = wn * 32 + bn * 8 + 2 * t;
            *(float2*)&Ct[r * PITCH_C + cc]       = make_float2(c[am][bn][0], c[am][bn][1]);
            *(float2*)&Ct[(r + 8) * PITCH_C + cc] = make_float2(c[am][bn][2], c[am][bn][3]);
        }
    }
    __syncthreads();

    if (modeK) {
        // normal rows (coalesced)
        for (int idx = tid; idx < 128 * 32; idx += 256) {
            const int r = idx >> 5, q = (idx & 31) * 4;
            const float4 cv = *(const float4*)&Ct[r * PITCH_C + q];
            const float sr = __ldg(&d_sq[r0 + r]);
            union { __half h[4]; uint2 u; } pk;
            pk.h[0] = __float2half_rn(__expf(-ALPHA * fmaxf(sr + __ldg(&d_sq[c0 + q + 0]) - 2.0f * cv.x, 0.0f)));
            pk.h[1] = __float2half_rn(__expf(-ALPHA * fmaxf(sr + __ldg(&d_sq[c0 + q + 1]) - 2.0f * cv.y, 0.0f)));
            pk.h[2] = __float2half_rn(__expf(-ALPHA * fmaxf(sr + __ldg(&d_sq[c0 + q + 2]) - 2.0f * cv.z, 0.0f)));
            pk.h[3] = __float2half_rn(__expf(-ALPHA * fmaxf(sr + __ldg(&d_sq[c0 + q + 3]) - 2.0f * cv.w, 0.0f)));
            *(uint2*)(d_Kh + (size_t)(r0 + r) * D + c0 + q) = pk.u;
        }
        // mirror rows: lanes along m -> conflict-free column reads of Ct
        for (int idx = tid; idx < 128 * 32; idx += 256) {
            const int m = idx & 127, q = (idx >> 7) * 4;
            const float sm = __ldg(&d_sq[c0 + m]);
            union { __half h[4]; uint2 u; } pk;
#pragma unroll
            for (int e = 0; e < 4; e++) {
                const float v = Ct[(q + e) * PITCH_C + m];
                pk.h[e] = __float2half_rn(__expf(-ALPHA * fmaxf(sm + __ldg(&d_sq[r0 + q + e]) - 2.0f * v, 0.0f)));
            }
            *(uint2*)(d_Kh + (size_t)(c0 + m) * D + r0 + q) = pk.u;
        }
    } else {
        for (int idx = tid; idx < 128 * 32; idx += 256) {
            const int r = idx >> 5, q = (idx & 31) * 4;
            *(float4*)(d_G + (size_t)(r0 + r) * D + c0 + q) = *(const float4*)&Ct[r * PITCH_C + q];
        }
        for (int idx = tid; idx < 128 * 32; idx += 256) {
            const int m = idx & 127, q = (idx >> 7) * 4;
            float4 v;
            v.x = Ct[(q + 0) * PITCH_C + m];
            v.y = Ct[(q + 1) * PITCH_C + m];
            v.z = Ct[(q + 2) * PITCH_C + m];
            v.w = Ct[(q + 3) * PITCH_C + m];
            *(float4*)(d_G + (size_t)(c0 + m) * D + r0 + q) = v;
        }
    }
}

// ---------------- rowsum of Ghat -> invr ----------------
__global__ void __launch_bounds__(256) rowsum() {
    const int row  = blockIdx.x * 8 + (threadIdx.x >> 5);
    const int lane = threadIdx.x & 31;
    const float4* g = (const float4*)(d_G + (size_t)row * D);
    float s = 0.f;
#pragma unroll
    for (int it = 0; it < D / 128; it++) {
        const float4 v = g[lane + 32 * it];
        s += (v.x + v.y) + (v.z + v.w);
    }
    s = warp_red(s);
    if (lane == 0) d_invr[row] = 1.0f / s;
}

// two interleaved fp16 row-dots against smem fp32 vector, f32x2 accumulation
__device__ __forceinline__ void row_dot2h(const __half* __restrict__ K0,
                                          const __half* __restrict__ K1,
                                          const float* sx, int lane,
                                          float& o0, float& o1) {
    const uint4* a = (const uint4*)K0;   // 8 halves per uint4, 256 per row
    const uint4* b = (const uint4*)K1;
    ull s0a = 0ULL, s0b = 0ULL, s1a = 0ULL, s1b = 0ULL;
#pragma unroll
    for (int it = 0; it < 8; it++) {
        const int o = lane + 32 * it;
        const uint4 k0 = __ldg(a + o);
        const uint4 k1 = __ldg(b + o);
        const ulonglong2 x01 = *(const ulonglong2*)(sx + o * 8);
        const ulonglong2 x23 = *(const ulonglong2*)(sx + o * 8 + 4);
        fma2(s0a, h2f2(k0.x), x01.x); fma2(s0b, h2f2(k0.y), x01.y);
        fma2(s0a, h2f2(k0.z), x23.x); fma2(s0b, h2f2(k0.w), x23.y);
        fma2(s1a, h2f2(k1.x), x01.x); fma2(s1b, h2f2(k1.y), x01.y);
        fma2(s1a, h2f2(k1.z), x23.x); fma2(s1b, h2f2(k1.w), x23.y);
    }
    const float2 p0 = up2(s0a), q0 = up2(s0b);
    const float2 p1 = up2(s1a), q1 = up2(s1b);
    o0 = warp_red((p0.x + p0.y) + (q0.x + q0.y));
    o1 = warp_red((p1.x + p1.y) + (q1.x + q1.y));
}

// ---------------- persistent Sinkhorn (K symmetric => K^T u == K u) -------------
// Phase A exploits u0 = ones: v1 = AB/(rowsum(K)+eps) needs NO initialization
// barrier and NO staging — and pre-warms this SM's K rows in L1 before the
// first grid barrier. Fast path (exit at cpt=1): 3 barriers total.
__global__ void __launch_bounds__(NT, 1) sinkhorn_kernel() {
    __shared__ float sx[D];
    __shared__ float sred[RPB];
    const int tid = threadIdx.x, bid = blockIdx.x;
    const int wid = tid >> 5, lane = tid & 31;
    const int row0 = bid * RPB + wid * 2;
    const float AB = 1.0f / (float)D;

    // ---- phase A: v = AB / (K·1 + eps)  (no global sync needed)
    for (int i = tid; i < D; i += NT) sx[i] = 1.0f;
    __syncthreads();
    {
        float s0, s1;
        row_dot2h(d_Kh + (size_t)row0 * D, d_Kh + (size_t)(row0 + 1) * D, sx, lane, s0, s1);
        if (lane == 0) {
            d_v[row0]     = AB / (s0 + EPSF);
            d_v[row0 + 1] = AB / (s1 + EPSF);
        }
    }
    unsigned ep = 1;
    gbar(ep, tid, bid); ep++;

    // ---- phase B: u = AB / (K v + eps)
    for (int i = tid; i < D / 4; i += NT)
        ((float4*)sx)[i] = __ldcg(((const float4*)d_v) + i);
    __syncthreads();
    {
        float s0, s1;
        row_dot2h(d_Kh + (size_t)row0 * D, d_Kh + (size_t)(row0 + 1) * D, sx, lane, s0, s1);
        if (lane == 0) {
            d_u[row0]     = AB / (s0 + EPSF);
            d_u[row0 + 1] = AB / (s1 + EPSF);
        }
    }
    gbar(ep, tid, bid); ep++;

    int cpt = 1;
    float err;
    // ---- phase C: err check at cpt=1
    {
        for (int i = tid; i < D / 4; i += NT)
            ((float4*)sx)[i] = __ldcg(((const float4*)d_u) + i);
        __syncthreads();
        float s0, s1;
        row_dot2h(d_Kh + (size_t)row0 * D, d_Kh + (size_t)(row0 + 1) * D, sx, lane, s0, s1);
        if (lane == 0) {
            sred[wid * 2]     = fabsf(__ldcg(&d_v[row0])     * s0 - AB);
            sred[wid * 2 + 1] = fabsf(__ldcg(&d_v[row0 + 1]) * s1 - AB);
        }
        __syncthreads();
        if (tid == 0) {
            float e = 0.f;
#pragma unroll
            for (int i = 0; i < RPB; i++) e += sred[i];
            d_errpart[bid] = e;     // chk = 0 slot
        }
        gbar(ep, tid, bid); ep++;
        // identical deterministic reduction in every block -> uniform exit
        float e = 0.f;
        for (int i = 0; i < NB; i++) e += __ldcg(&d_errpart[i]);
        err = e;
    }

    // ---- generic continuation (cpt >= 2)
    while (err > STOPTHR && cpt < MAXIT) {
        // v = AB / (K u + eps)
        for (int i = tid; i < D / 4; i += NT)
            ((float4*)sx)[i] = __ldcg(((const float4*)d_u) + i);
        __syncthreads();
        {
            float s0, s1;
            row_dot2h(d_Kh + (size_t)row0 * D, d_Kh + (size_t)(row0 + 1) * D, sx, lane, s0, s1);
            if (lane == 0) {
                d_v[row0]     = AB / (s0 + EPSF);
                d_v[row0 + 1] = AB / (s1 + EPSF);
            }
        }
        gbar(ep, tid, bid); ep++;

        // u = AB / (K v + eps)
        for (int i = tid; i < D / 4; i += NT)
            ((float4*)sx)[i] = __ldcg(((const float4*)d_v) + i);
        __syncthreads();
        {
            float s0, s1;
            row_dot2h(d_Kh + (size_t)row0 * D, d_Kh + (size_t)(row0 + 1) * D, sx, lane, s0, s1);
            if (lane == 0) {
                d_u[row0]     = AB / (s0 + EPSF);
                d_u[row0 + 1] = AB / (s1 + EPSF);
            }
        }
        gbar(ep, tid, bid); ep++;

        cpt++;
        if (cpt % 50 == 1) {
            for (int i = tid; i < D / 4; i += NT)
                ((float4*)sx)[i] = __ldcg(((const float4*)d_u) + i);
            __syncthreads();
            {
                float s0, s1;
                row_dot2h(d_Kh + (size_t)row0 * D, d_Kh + (size_t)(row0 + 1) * D, sx, lane, s0, s1);
                if (lane == 0) {
                    sred[wid * 2]     = fabsf(__ldcg(&d_v[row0])     * s0 - AB);
                    sred[wid * 2 + 1] = fabsf(__ldcg(&d_v[row0 + 1]) * s1 - AB);
                }
            }
            __syncthreads();
            const int chk = cpt / 50;
            if (tid == 0) {
                float e = 0.f;
#pragma unroll
                for (int i = 0; i < RPB; i++) e += sred[i];
                d_errpart[chk * NB + bid] = e;
            }
            gbar(ep, tid, bid); ep++;
            float e = 0.f;
            for (int i = 0; i < NB; i++) e += __ldcg(&d_errpart[chk * NB + i]);
            err = e;
        }
    }
}

// ---------------- KL reduction ----------------
// Qt_ij = max(u_i K_ij v_j, 1e-6), S = sum Qt, P_ij = G_ij*(invr_i+invr_j)/2
// kl = sum P*log(P/Qt) + log(S) * sum P
__global__ void __launch_bounds__(NT) kl_partial() {
    const int tid = threadIdx.x;
    constexpr int TOT8 = D * D / 8;
    const int stride = NKB * NT;
    const uint4*  Kv = (const uint4*)d_Kh;
    const float4* Gv = (const float4*)d_G;
    const float4* Vv = (const float4*)d_v;
    const float4* Rv = (const float4*)d_invr;

    float sS = 0.f, sP = 0.f, sK = 0.f;
    for (int g8 = blockIdx.x * NT + tid; g8 < TOT8; g8 += stride) {
        const int i  = g8 >> 8;
        const int c8 = g8 & 255;
        const uint4 kh = Kv[g8];
        const float4 g0 = Gv[g8 * 2];
        const float4 g1 = Gv[g8 * 2 + 1];
        const float4 v0 = Vv[c8 * 2];
        const float4 v1 = Vv[c8 * 2 + 1];
        const float4 r0 = Rv[c8 * 2];
        const float4 r1 = Rv[c8 * 2 + 1];
        const float ui  = d_u[i];
        const float iri = d_invr[i];

        const float2 ka = __half22float2(*(const __half2*)&kh.x);
        const float2 kb = __half22float2(*(const __half2*)&kh.y);
        const float2 kc = __half22float2(*(const __half2*)&kh.z);
        const float2 kd = __half22float2(*(const __half2*)&kh.w);

        float q, p;
        q = fmaxf(ui * ka.x * v0.x, 1e-6f); p = g0.x * (0.5f * (iri + r0.x));
        sS += q; sP += p; sK += p * __logf(__fdividef(p, q));
        q = fmaxf(ui * ka.y * v0.y, 1e-6f); p = g0.y * (0.5f * (iri + r0.y));
        sS += q; sP += p; sK += p * __logf(__fdividef(p, q));
        q = fmaxf(ui * kb.x * v0.z, 1e-6f); p = g0.z * (0.5f * (iri + r0.z));
        sS += q; sP += p; sK += p * __logf(__fdividef(p, q));
        q = fmaxf(ui * kb.y * v0.w, 1e-6f); p = g0.w * (0.5f * (iri + r0.w));
        sS += q; sP += p; sK += p * __logf(__fdividef(p, q));
        q = fmaxf(ui * kc.x * v1.x, 1e-6f); p = g1.x * (0.5f * (iri + r1.x));
        sS += q; sP += p; sK += p * __logf(__fdividef(p, q));
        q = fmaxf(ui * kc.y * v1.y, 1e-6f); p = g1.y * (0.5f * (iri + r1.y));
        sS += q; sP += p; sK += p * __logf(__fdividef(p, q));
        q = fmaxf(ui * kd.x * v1.z, 1e-6f); p = g1.z * (0.5f * (iri + r1.z));
        sS += q; sP += p; sK += p * __logf(__fdividef(p, q));
        q = fmaxf(ui * kd.y * v1.w, 1e-6f); p = g1.w * (0.5f * (iri + r1.w));
        sS += q; sP += p; sK += p * __logf(__fdividef(p, q));
    }

    __shared__ double sd[NT];
    const double vals[3] = {(double)sS, (double)sP, (double)sK};
#pragma unroll
    for (int t = 0; t < 3; t++) {
        sd[tid] = vals[t];
        __syncthreads();
        for (int o = NT / 2; o; o >>= 1) {
            if (tid < o) sd[tid] += sd[tid + o];
            __syncthreads();
        }
        if (tid == 0) d_part[t * NKB + blockIdx.x] = sd[0];
        __syncthreads();
    }
}

__global__ void __launch_bounds__(NKB) finalize(float* out) {
    __shared__ double sd[NKB];
    const int tid = threadIdx.x;
    double acc[3];
#pragma unroll
    for (int t = 0; t < 3; t++) {
        sd[tid] = d_part[t * NKB + tid];
        __syncthreads();
        for (int o = NKB / 2; o; o >>= 1) {
            if (tid < o) sd[tid] += sd[tid + o];
            __syncthreads();
        }
        acc[t] = sd[0];
        __syncthreads();
    }
    if (tid == 0) out[0] = (float)(acc[2] + log(acc[0]) * acc[1]);
}

// ---------------- launch ----------------
extern "C" void kernel_launch(void* const* d_in, const int* in_sizes, int n_in,
                              void* d_out, int out_size) {
    const float* theta = (const float*)d_in[0];
    const float* emb   = (const float*)d_in[1];
    float* out = (float*)d_out;

    cudaFuncSetAttribute((const void*)gemm_sym,
                         cudaFuncAttributeMaxDynamicSharedMemorySize, GEMM_SMEM);

    prep<<<D, F>>>(theta, emb);
    gemm_sym<<<2 * NBLK, 256, GEMM_SMEM>>>(theta);
    rowsum<<<D / 8, 256>>>();
    sinkhorn_kernel<<<NB, NT>>>();
    kl_partial<<<NKB, NT>>>();
    finalize<<<1, NKB>>>(out);
}

// round 14
// speedup vs baseline: 2.1701x; 2.1701x over previous
#include <cuda_runtime.h>
#include <cuda_fp16.h>
#include <cstdint>
#include <math.h>

// Problem constants
constexpr int   D       = 2048;
constexpr int   F       = 256;
constexpr float ALPHA   = 0.005f;   // SINKHORN_ALPHA
constexpr float STOPTHR = 0.005f;
constexpr float EPSF    = 1e-16f;
constexpr int   MAXIT   = 500;

// Launch shapes
constexpr int NB   = 128;         // persistent fallback blocks
constexpr int NT   = 256;
constexpr int RPB  = D / NB;      // 16 rows per block (fallback)
constexpr int NKB  = 256;
constexpr int NBLK = 136;         // triangular 128x128 tile count: 16*17/2
constexpr int NSB  = 256;         // sink phase kernels: 256 blocks x 8 warp-rows

// GEMM smem: two 128x68 u32 tiles (tf32, K-chunk=64) -> 69.6KB -> 2 CTAs/SM
constexpr int PITCH2  = 68;
constexpr int TILEW2  = 128 * PITCH2;
constexpr int PITCH_C = 132;
constexpr int GEMM_SMEM = 2 * TILEW2 * 4;     // 69632 bytes

typedef unsigned long long ull;

// ---------------- device scratch ----------------
__device__ __half d_Kh[(size_t)D * D];    // 8 MB: K = exp(-alpha*C), fp16, symmetric
__device__ float  d_G[(size_t)D * D];     // 16 MB: Ghat = ehat ehat^T, symmetric
__device__ float  d_ehat[D * F];
__device__ float  d_sq[D];
__device__ float  d_invr[D];
__device__ float  d_u[D];
__device__ float  d_v[D];
__device__ float  d_errpart[12 * NB];     // fallback err partials
__device__ float  d_errp2[NSB];           // phase-kernel err partials
__device__ float  d_errglob;              // err after cpt=1 (uniform exit flag)
__device__ double d_part[3 * NKB];
__device__ unsigned d_cnt;                // fallback grid-barrier counter

// ---------------- f32x2 helpers ----------------
__device__ __forceinline__ ull pk2(float lo, float hi) {
    ull r; asm("mov.b64 %0,{%1,%2};" : "=l"(r) : "f"(lo), "f"(hi)); return r;
}
__device__ __forceinline__ float2 up2(ull v) {
    float2 f; asm("mov.b64 {%0,%1},%2;" : "=f"(f.x), "=f"(f.y) : "l"(v)); return f;
}
__device__ __forceinline__ void fma2(ull& d, ull a, ull b) {
    asm("fma.rn.f32x2 %0,%1,%2,%0;" : "+l"(d) : "l"(a), "l"(b));
}
__device__ __forceinline__ ull h2f2(unsigned h) {
    const float2 f = __half22float2(*reinterpret_cast<const __half2*>(&h));
    return pk2(f.x, f.y);
}

// ---------------- tf32 mma helpers ----------------
__device__ __forceinline__ uint32_t f2tf32(float f) {
    uint32_t r; asm("cvt.rna.tf32.f32 %0,%1;" : "=r"(r) : "f"(f)); return r;
}
__device__ __forceinline__ void mma_tf32(float* c, const uint32_t* a, const uint32_t* b) {
    asm("mma.sync.aligned.m16n8k8.row.col.f32.tf32.tf32.f32 "
        "{%0,%1,%2,%3},{%4,%5,%6,%7},{%8,%9},{%0,%1,%2,%3};"
        : "+f"(c[0]), "+f"(c[1]), "+f"(c[2]), "+f"(c[3])
        : "r"(a[0]), "r"(a[1]), "r"(a[2]), "r"(a[3]), "r"(b[0]), "r"(b[1]));
}

__device__ __forceinline__ float warp_red(float s) {
#pragma unroll
    for (int o = 16; o; o >>= 1) s += __shfl_xor_sync(0xffffffffu, s, o);
    return s;
}

// R12 grid barrier (best measured): single counter, RED arrive, single poller.
// Used ONLY by the fallback kernel (not on the fast path).
__device__ __forceinline__ void gbar(unsigned target, int tid) {
    __syncthreads();
    if (tid == 0) {
        asm volatile("red.release.gpu.global.add.u32 [%0], 1;"
                     :: "l"(&d_cnt) : "memory");
        unsigned v;
        int spins = 0;
        do {
            asm volatile("ld.acquire.gpu.global.u32 %0, [%1];"
                         : "=r"(v) : "l"(&d_cnt) : "memory");
            if (++spins > 100000) __nanosleep(128);
        } while (v < target);
    }
    __syncthreads();
}

// ---------------- prep: sq, ehat, counter reset ----------------
__global__ void __launch_bounds__(F) prep(const float* __restrict__ theta,
                                          const float* __restrict__ emb) {
    const int row = blockIdx.x, tid = threadIdx.x;
    if (tid == 0 && row == 0) d_cnt = 0u;

    const float t = theta[row * F + tid];
    const float e = emb[row * F + tid];
    float a = t * t, b = e * e;
#pragma unroll
    for (int o = 16; o; o >>= 1) {
        a += __shfl_xor_sync(0xffffffffu, a, o);
        b += __shfl_xor_sync(0xffffffffu, b, o);
    }
    __shared__ float sa[8], sb[8];
    __shared__ float s_inv;
    const int wid = tid >> 5, lane = tid & 31;
    if (lane == 0) { sa[wid] = a; sb[wid] = b; }
    __syncthreads();
    if (tid == 0) {
        float ta = 0.f, tb = 0.f;
#pragma unroll
        for (int i = 0; i < 8; i++) { ta += sa[i]; tb += sb[i]; }
        d_sq[row] = ta;
        s_inv = 1.0f / sqrtf(tb);
    }
    __syncthreads();
    d_ehat[row * F + tid] = e * s_inv;
}

// ---------------- symmetric fused GEMM — tf32 tensor cores (R12, unchanged) ----
__global__ void __launch_bounds__(256, 2) gemm_sym(const float* __restrict__ theta) {
    extern __shared__ uint32_t smw[];
    uint32_t* As = smw;
    uint32_t* Bs = smw + TILEW2;

    const int bid = blockIdx.x;
    const bool modeK = (bid < NBLK);
    const int tb = modeK ? bid : bid - NBLK;
    const float* __restrict__ X = modeK ? theta : (const float*)d_ehat;

    int ib = (int)((sqrtf(8.0f * (float)tb + 1.0f) - 1.0f) * 0.5f);
    while ((ib + 1) * (ib + 2) / 2 <= tb) ib++;
    while (ib * (ib + 1) / 2 > tb) ib--;
    const int jb = tb - ib * (ib + 1) / 2;
    const int r0 = ib * 128, c0 = jb * 128;

    const int tid  = threadIdx.x;
    const int wid  = tid >> 5, lane = tid & 31;
    const int g    = lane >> 2, t = lane & 3;
    const int wm   = wid >> 2,  wn = wid & 3;

    float c[4][4][4];
#pragma unroll
    for (int am = 0; am < 4; am++)
#pragma unroll
        for (int bn = 0; bn < 4; bn++)
#pragma unroll
            for (int e = 0; e < 4; e++) c[am][bn][e] = 0.0f;

    for (int kc = 0; kc < 4; kc++) {
        for (int idx = tid; idx < 128 * 16; idx += 256) {
            const int r = idx >> 4, q = (idx & 15) * 4;
            const float4 av = *(const float4*)(X + (size_t)(r0 + r) * F + kc * 64 + q);
            uint4 ua;
            ua.x = f2tf32(av.x); ua.y = f2tf32(av.y);
            ua.z = f2tf32(av.z); ua.w = f2tf32(av.w);
            *(uint4*)&As[r * PITCH2 + q] = ua;
            const float4 bv = *(const float4*)(X + (size_t)(c0 + r) * F + kc * 64 + q);
            uint4 ub;
            ub.x = f2tf32(bv.x); ub.y = f2tf32(bv.y);
            ub.z = f2tf32(bv.z); ub.w = f2tf32(bv.w);
            *(uint4*)&Bs[r * PITCH2 + q] = ub;
        }
        __syncthreads();

#pragma unroll 4
        for (int s = 0; s < 8; s++) {
            uint32_t a[4][4], b[4][2];
#pragma unroll
            for (int am = 0; am < 4; am++) {
                const uint32_t* p = As + (wm * 64 + am * 16 + g) * PITCH2 + s * 8 + t;
                a[am][0] = p[0];
                a[am][1] = p[8 * PITCH2];
                a[am][2] = p[4];
                a[am][3] = p[8 * PITCH2 + 4];
            }
#pragma unroll
            for (int bn = 0; bn < 4; bn++) {
                const uint32_t* p = Bs + (wn * 32 + bn * 8 + g) * PITCH2 + s * 8 + t;
                b[bn][0] = p[0];
                b[bn][1] = p[4];
            }
#pragma unroll
            for (int am = 0; am < 4; am++)
#pragma unroll
                for (int bn = 0; bn < 4; bn++)
                    mma_tf32(c[am][bn], a[am], b[bn]);
        }
        __syncthreads();
    }

    float* Ct = (float*)smw;
#pragma unroll
    for (int am = 0; am < 4; am++) {
        const int r = wm * 64 + am * 16 + g;
#pragma unroll
        for (int bn = 0; bn < 4; bn++) {
            const int cc = wn * 32 + bn * 8 + 2 * t;
            *(float2*)&Ct[r * PITCH_C + cc]       = make_float2(c[am][bn][0], c[am][bn][1]);
            *(float2*)&Ct[(r + 8) * PITCH_C + cc] = make_float2(c[am][bn][2], c[am][bn][3]);
        }
    }
    __syncthreads();

    if (modeK) {
        for (int idx = tid; idx < 128 * 32; idx += 256) {
            const int r = idx >> 5, q = (idx & 31) * 4;
            const float4 cv = *(const float4*)&Ct[r * PITCH_C + q];
            const float sr = __ldg(&d_sq[r0 + r]);
            union { __half h[4]; uint2 u; } pk;
            pk.h[0] = __float2half_rn(__expf(-ALPHA * fmaxf(sr + __ldg(&d_sq[c0 + q + 0]) - 2.0f * cv.x, 0.0f)));
            pk.h[1] = __float2half_rn(__expf(-ALPHA * fmaxf(sr + __ldg(&d_sq[c0 + q + 1]) - 2.0f * cv.y, 0.0f)));
            pk.h[2] = __float2half_rn(__expf(-ALPHA * fmaxf(sr + __ldg(&d_sq[c0 + q + 2]) - 2.0f * cv.z, 0.0f)));
            pk.h[3] = __float2half_rn(__expf(-ALPHA * fmaxf(sr + __ldg(&d_sq[c0 + q + 3]) - 2.0f * cv.w, 0.0f)));
            *(uint2*)(d_Kh + (size_t)(r0 + r) * D + c0 + q) = pk.u;
        }
        for (int idx = tid; idx < 128 * 32; idx += 256) {
            const int m = idx & 127, q = (idx >> 7) * 4;
            const float sm = __ldg(&d_sq[c0 + m]);
            union { __half h[4]; uint2 u; } pk;
#pragma unroll
            for (int e = 0; e < 4; e++) {
                const float v = Ct[(q + e) * PITCH_C + m];
                pk.h[e] = __float2half_rn(__expf(-ALPHA * fmaxf(sm + __ldg(&d_sq[r0 + q + e]) - 2.0f * v, 0.0f)));
            }
            *(uint2*)(d_Kh + (size_t)(c0 + m) * D + r0 + q) = pk.u;
        }
    } else {
        for (int idx = tid; idx < 128 * 32; idx += 256) {
            const int r = idx >> 5, q = (idx & 31) * 4;
            *(float4*)(d_G + (size_t)(r0 + r) * D + c0 + q) = *(const float4*)&Ct[r * PITCH_C + q];
        }
        for (int idx = tid; idx < 128 * 32; idx += 256) {
            const int m = idx & 127, q = (idx >> 7) * 4;
            float4 v;
            v.x = Ct[(q + 0) * PITCH_C + m];
            v.y = Ct[(q + 1) * PITCH_C + m];
            v.z = Ct[(q + 2) * PITCH_C + m];
            v.w = Ct[(q + 3) * PITCH_C + m];
            *(float4*)(d_G + (size_t)(c0 + m) * D + r0 + q) = v;
        }
    }
}

// ---------------- rowsum of Ghat -> invr ----------------
__global__ void __launch_bounds__(256) rowsum() {
    const int row  = blockIdx.x * 8 + (threadIdx.x >> 5);
    const int lane = threadIdx.x & 31;
    const float4* g = (const float4*)(d_G + (size_t)row * D);
    float s = 0.f;
#pragma unroll
    for (int it = 0; it < D / 128; it++) {
        const float4 v = g[lane + 32 * it];
        s += (v.x + v.y) + (v.z + v.w);
    }
    s = warp_red(s);
    if (lane == 0) d_invr[row] = 1.0f / s;
}

// single fp16 row-dot vs smem fp32 vector (warp-collective)
__device__ __forceinline__ float row_dot1h(const __half* __restrict__ K0,
                                           const float* sx, int lane) {
    const uint4* a = (const uint4*)K0;
    ull sa = 0ULL, sb = 0ULL;
#pragma unroll
    for (int it = 0; it < 8; it++) {
        const int o = lane + 32 * it;
        const uint4 k0 = __ldg(a + o);
        const ulonglong2 x01 = *(const ulonglong2*)(sx + o * 8);
        const ulonglong2 x23 = *(const ulonglong2*)(sx + o * 8 + 4);
        fma2(sa, h2f2(k0.x), x01.x); fma2(sb, h2f2(k0.y), x01.y);
        fma2(sa, h2f2(k0.z), x23.x); fma2(sb, h2f2(k0.w), x23.y);
    }
    const float2 p = up2(sa), q = up2(sb);
    return warp_red((p.x + p.y) + (q.x + q.y));
}

// two interleaved fp16 row-dots (fallback kernel)
__device__ __forceinline__ void row_dot2h(const __half* __restrict__ K0,
                                          const __half* __restrict__ K1,
                                          const float* sx, int lane,
                                          float& o0, float& o1) {
    const uint4* a = (const uint4*)K0;
    const uint4* b = (const uint4*)K1;
    ull s0a = 0ULL, s0b = 0ULL, s1a = 0ULL, s1b = 0ULL;
#pragma unroll
    for (int it = 0; it < 8; it++) {
        const int o = lane + 32 * it;
        const uint4 k0 = __ldg(a + o);
        const uint4 k1 = __ldg(b + o);
        const ulonglong2 x01 = *(const ulonglong2*)(sx + o * 8);
        const ulonglong2 x23 = *(const ulonglong2*)(sx + o * 8 + 4);
        fma2(s0a, h2f2(k0.x), x01.x); fma2(s0b, h2f2(k0.y), x01.y);
        fma2(s0a, h2f2(k0.z), x23.x); fma2(s0b, h2f2(k0.w), x23.y);
        fma2(s1a, h2f2(k1.x), x01.x); fma2(s1b, h2f2(k1.y), x01.y);
        fma2(s1a, h2f2(k1.z), x23.x); fma2(s1b, h2f2(k1.w), x23.y);
    }
    const float2 p0 = up2(s0a), q0 = up2(s0b);
    const float2 p1 = up2(s1a), q1 = up2(s1b);
    o0 = warp_red((p0.x + p0.y) + (q0.x + q0.y));
    o1 = warp_red((p1.x + p1.y) + (q1.x + q1.y));
}

// ---------------- Sinkhorn fast path: kernel-boundary syncs, no grid barriers ----
// u0 = ones  =>  v1 = AB / (rowsum(K) + eps)   [one warp per row]
__global__ void __launch_bounds__(NT) sink_v() {
    const int row  = blockIdx.x * 8 + (threadIdx.x >> 5);
    const int lane = threadIdx.x & 31;
    const uint4* a = (const uint4*)(d_Kh + (size_t)row * D);
    float s = 0.f;
#pragma unroll
    for (int it = 0; it < 8; it++) {
        const uint4 k = __ldg(a + lane + 32 * it);
        const float2 ka = __half22float2(*(const __half2*)&k.x);
        const float2 kb = __half22float2(*(const __half2*)&k.y);
        const float2 kc = __half22float2(*(const __half2*)&k.z);
        const float2 kd = __half22float2(*(const __half2*)&k.w);
        s += ((ka.x + ka.y) + (kb.x + kb.y)) + ((kc.x + kc.y) + (kd.x + kd.y));
    }
    s = warp_red(s);
    if (lane == 0) d_v[row] = (1.0f / (float)D) / (s + EPSF);
}

// u = AB / (K v + eps)
__global__ void __launch_bounds__(NT) sink_u() {
    __shared__ float sx[D];
    const int tid = threadIdx.x, lane = tid & 31;
    const int row = blockIdx.x * 8 + (tid >> 5);
    for (int i = tid; i < D / 4; i += NT)
        ((float4*)sx)[i] = __ldcg(((const float4*)d_v) + i);
    __syncthreads();
    const float s = row_dot1h(d_Kh + (size_t)row * D, sx, lane);
    if (lane == 0) d_u[row] = (1.0f / (float)D) / (s + EPSF);
}

// err partials: sum_rows | v_r * (K u)_r - AB | per block
__global__ void __launch_bounds__(NT) sink_err() {
    __shared__ float sx[D];
    __shared__ float sr[8];
    const int tid = threadIdx.x, lane = tid & 31, wid = tid >> 5;
    const int row = blockIdx.x * 8 + wid;
    for (int i = tid; i < D / 4; i += NT)
        ((float4*)sx)[i] = __ldcg(((const float4*)d_u) + i);
    __syncthreads();
    const float s = row_dot1h(d_Kh + (size_t)row * D, sx, lane);
    if (lane == 0) sr[wid] = fabsf(__ldcg(&d_v[row]) * s - 1.0f / (float)D);
    __syncthreads();
    if (tid == 0) {
        float e = 0.f;
#pragma unroll
        for (int i = 0; i < 8; i++) e += sr[i];
        d_errp2[blockIdx.x] = e;
    }
}

// deterministic tree-reduce of the NSB err partials -> d_errglob
__global__ void __launch_bounds__(NSB) sink_err_fin() {
    __shared__ float sd[NSB];
    const int tid = threadIdx.x;
    sd[tid] = d_errp2[tid];
    __syncthreads();
    for (int o = NSB / 2; o; o >>= 1) {
        if (tid < o) sd[tid] += sd[tid + o];
        __syncthreads();
    }
    if (tid == 0) d_errglob = sd[0];
}

// ---------------- persistent fallback (runs loop ONLY if not converged) --------
__global__ void __launch_bounds__(NT, 1) sink_loop() {
    float err = __ldcg(&d_errglob);           // same value in every block
    if (err <= STOPTHR) return;               // uniform early exit (fast path)

    __shared__ float sx[D];
    __shared__ float sred[RPB];
    const int tid = threadIdx.x, bid = blockIdx.x;
    const int wid = tid >> 5, lane = tid & 31;
    const int row0 = bid * RPB + wid * 2;
    const float AB = 1.0f / (float)D;

    unsigned ep = 1;
    int cpt = 1;
    while (err > STOPTHR && cpt < MAXIT) {
        // v = AB / (K u + eps)
        for (int i = tid; i < D / 4; i += NT)
            ((float4*)sx)[i] = __ldcg(((const float4*)d_u) + i);
        __syncthreads();
        {
            float s0, s1;
            row_dot2h(d_Kh + (size_t)row0 * D, d_Kh + (size_t)(row0 + 1) * D, sx, lane, s0, s1);
            if (lane == 0) {
                d_v[row0]     = AB / (s0 + EPSF);
                d_v[row0 + 1] = AB / (s1 + EPSF);
            }
        }
        gbar(ep * NB, tid); ep++;

        // u = AB / (K v + eps)
        for (int i = tid; i < D / 4; i += NT)
            ((float4*)sx)[i] = __ldcg(((const float4*)d_v) + i);
        __syncthreads();
        {
            float s0, s1;
            row_dot2h(d_Kh + (size_t)row0 * D, d_Kh + (size_t)(row0 + 1) * D, sx, lane, s0, s1);
            if (lane == 0) {
                d_u[row0]     = AB / (s0 + EPSF);
                d_u[row0 + 1] = AB / (s1 + EPSF);
            }
        }
        gbar(ep * NB, tid); ep++;

        cpt++;
        if (cpt % 50 == 1) {
            for (int i = tid; i < D / 4; i += NT)
                ((float4*)sx)[i] = __ldcg(((const float4*)d_u) + i);
            __syncthreads();
            {
                float s0, s1;
                row_dot2h(d_Kh + (size_t)row0 * D, d_Kh + (size_t)(row0 + 1) * D, sx, lane, s0, s1);
                if (lane == 0) {
                    sred[wid * 2]     = fabsf(__ldcg(&d_v[row0])     * s0 - AB);
                    sred[wid * 2 + 1] = fabsf(__ldcg(&d_v[row0 + 1]) * s1 - AB);
                }
            }
            __syncthreads();
            const int chk = cpt / 50;
            if (tid == 0) {
                float e = 0.f;
#pragma unroll
                for (int i = 0; i < RPB; i++) e += sred[i];
                d_errpart[chk * NB + bid] = e;
            }
            gbar(ep * NB, tid); ep++;
            // identical deterministic reduction in every block -> uniform exit
            float e = 0.f;
            for (int i = 0; i < NB; i++) e += __ldcg(&d_errpart[chk * NB + i]);
            err = e;
        }
    }
}

// ---------------- KL reduction ----------------
__global__ void __launch_bounds__(NT) kl_partial() {
    const int tid = threadIdx.x;
    constexpr int TOT8 = D * D / 8;
    const int stride = NKB * NT;
    const uint4*  Kv = (const uint4*)d_Kh;
    const float4* Gv = (const float4*)d_G;
    const float4* Vv = (const float4*)d_v;
    const float4* Rv = (const float4*)d_invr;

    float sS = 0.f, sP = 0.f, sK = 0.f;
    for (int g8 = blockIdx.x * NT + tid; g8 < TOT8; g8 += stride) {
        const int i  = g8 >> 8;
        const int c8 = g8 & 255;
        const uint4 kh = Kv[g8];
        const float4 g0 = Gv[g8 * 2];
        const float4 g1 = Gv[g8 * 2 + 1];
        const float4 v0 = Vv[c8 * 2];
        const float4 v1 = Vv[c8 * 2 + 1];
        const float4 r0 = Rv[c8 * 2];
        const float4 r1 = Rv[c8 * 2 + 1];
        const float ui  = d_u[i];
        const float iri = d_invr[i];

        const float2 ka = __half22float2(*(const __half2*)&kh.x);
        const float2 kb = __half22float2(*(const __half2*)&kh.y);
        const float2 kc = __half22float2(*(const __half2*)&kh.z);
        const float2 kd = __half22float2(*(const __half2*)&kh.w);

        float q, p;
        q = fmaxf(ui * ka.x * v0.x, 1e-6f); p = g0.x * (0.5f * (iri + r0.x));
        sS += q; sP += p; sK += p * __logf(__fdividef(p, q));
        q = fmaxf(ui * ka.y * v0.y, 1e-6f); p = g0.y * (0.5f * (iri + r0.y));
        sS += q; sP += p; sK += p * __logf(__fdividef(p, q));
        q = fmaxf(ui * kb.x * v0.z, 1e-6f); p = g0.z * (0.5f * (iri + r0.z));
        sS += q; sP += p; sK += p * __logf(__fdividef(p, q));
        q = fmaxf(ui * kb.y * v0.w, 1e-6f); p = g0.w * (0.5f * (iri + r0.w));
        sS += q; sP += p; sK += p * __logf(__fdividef(p, q));
        q = fmaxf(ui * kc.x * v1.x, 1e-6f); p = g1.x * (0.5f * (iri + r1.x));
        sS += q; sP += p; sK += p * __logf(__fdividef(p, q));
        q = fmaxf(ui * kc.y * v1.y, 1e-6f); p = g1.y * (0.5f * (iri + r1.y));
        sS += q; sP += p; sK += p * __logf(__fdividef(p, q));
        q = fmaxf(ui * kd.x * v1.z, 1e-6f); p = g1.z * (0.5f * (iri + r1.z));
        sS += q; sP += p; sK += p * __logf(__fdividef(p, q));
        q = fmaxf(ui * kd.y * v1.w, 1e-6f); p = g1.w * (0.5f * (iri + r1.w));
        sS += q; sP += p; sK += p * __logf(__fdividef(p, q));
    }

    __shared__ double sd[NT];
    const double vals[3] = {(double)sS, (double)sP, (double)sK};
#pragma unroll
    for (int t = 0; t < 3; t++) {
        sd[tid] = vals[t];
        __syncthreads();
        for (int o = NT / 2; o; o >>= 1) {
            if (tid < o) sd[tid] += sd[tid + o];
            __syncthreads();
        }
        if (tid == 0) d_part[t * NKB + blockIdx.x] = sd[0];
        __syncthreads();
    }
}

__global__ void __launch_bounds__(NKB) finalize(float* out) {
    __shared__ double sd[NKB];
    const int tid = threadIdx.x;
    double acc[3];
#pragma unroll
    for (int t = 0; t < 3; t++) {
        sd[tid] = d_part[t * NKB + tid];
        __syncthreads();
        for (int o = NKB / 2; o; o >>= 1) {
            if (tid < o) sd[tid] += sd[tid + o];
            __syncthreads();
        }
        acc[t] = sd[0];
        __syncthreads();
    }
    if (tid == 0) out[0] = (float)(acc[2] + log(acc[0]) * acc[1]);
}

// ---------------- launch ----------------
extern "C" void kernel_launch(void* const* d_in, const int* in_sizes, int n_in,
                              void* d_out, int out_size) {
    const float* theta = (const float*)d_in[0];
    const float* emb   = (const float*)d_in[1];
    float* out = (float*)d_out;

    cudaFuncSetAttribute((const void*)gemm_sym,
                         cudaFuncAttributeMaxDynamicSharedMemorySize, GEMM_SMEM);

    prep<<<D, F>>>(theta, emb);
    gemm_sym<<<2 * NBLK, 256, GEMM_SMEM>>>(theta);
    rowsum<<<D / 8, 256>>>();
    sink_v<<<NSB, NT>>>();          // v1 (u0 = ones) — kernel boundary = sync
    sink_u<<<NSB, NT>>>();          // u1
    sink_err<<<NSB, NT>>>();        // err partials at cpt=1
    sink_err_fin<<<1, NSB>>>();     // deterministic err -> d_errglob
    sink_loop<<<NB, NT>>>();        // no-op if converged; full loop otherwise
    kl_partial<<<NKB, NT>>>();
    finalize<<<1, NKB>>>(out);
}